// round 1
// baseline (speedup 1.0000x reference)
#include <cuda_runtime.h>
#include <math.h>

#define C_DIM   128000
#define C_VEC   (C_DIM / 4)      // 32000 float4 per row
#define THREADS 256

struct Top2 {
    float m1, m2;
    int   i1, i2;
};

__device__ __forceinline__ void top2_push(Top2& t, float v, int idx) {
    if (v > t.m1) {
        t.m2 = t.m1; t.i2 = t.i1;
        t.m1 = v;    t.i1 = idx;
    } else if (v > t.m2) {
        t.m2 = v;    t.i2 = idx;
    }
}

__device__ __forceinline__ void top2_merge(Top2& a, const Top2& b) {
    // merge b into a
    if (b.m1 > a.m1) {
        // b.m1 becomes new max; runner-up is max(a.m1, b.m2)
        float nm2; int ni2;
        if (a.m1 > b.m2) { nm2 = a.m1; ni2 = a.i1; }
        else             { nm2 = b.m2; ni2 = b.i2; }
        a.m2 = nm2; a.i2 = ni2;
        a.m1 = b.m1; a.i1 = b.i1;
    } else {
        // a.m1 stays max; runner-up is max(a.m2, b.m1)
        if (b.m1 > a.m2) { a.m2 = b.m1; a.i2 = b.i1; }
    }
}

__global__ __launch_bounds__(THREADS, 8)
void fused_margin_kernel(const float* __restrict__ logits,
                         const long long* __restrict__ y,
                         float* __restrict__ out) {
    const int row = blockIdx.x;
    const float4* __restrict__ p =
        reinterpret_cast<const float4*>(logits + (size_t)row * C_DIM);

    const int tid = threadIdx.x;

    float sum = 0.0f;
    Top2 t;
    t.m1 = -INFINITY; t.m2 = -INFINITY; t.i1 = -1; t.i2 = -1;

    // 32000 / 256 = 125 iterations; unroll by 5 for MLP
    #pragma unroll 5
    for (int j = tid; j < C_VEC; j += THREADS) {
        float4 v = __ldg(p + j);
        int base = j * 4;
        sum += __expf(v.x);
        sum += __expf(v.y);
        sum += __expf(v.z);
        sum += __expf(v.w);
        top2_push(t, v.x, base + 0);
        top2_push(t, v.y, base + 1);
        top2_push(t, v.z, base + 2);
        top2_push(t, v.w, base + 3);
    }

    // ---- warp reduction ----
    const unsigned FULL = 0xFFFFFFFFu;
    #pragma unroll
    for (int off = 16; off > 0; off >>= 1) {
        sum += __shfl_xor_sync(FULL, sum, off);
        Top2 o;
        o.m1 = __shfl_xor_sync(FULL, t.m1, off);
        o.m2 = __shfl_xor_sync(FULL, t.m2, off);
        o.i1 = __shfl_xor_sync(FULL, t.i1, off);
        o.i2 = __shfl_xor_sync(FULL, t.i2, off);
        top2_merge(t, o);
    }

    // ---- cross-warp reduction via shared memory ----
    __shared__ float s_sum[THREADS / 32];
    __shared__ Top2  s_top[THREADS / 32];

    const int wid = tid >> 5;
    const int lid = tid & 31;
    if (lid == 0) {
        s_sum[wid] = sum;
        s_top[wid] = t;
    }
    __syncthreads();

    if (wid == 0) {
        const int nw = THREADS / 32;
        float fsum = (lid < nw) ? s_sum[lid] : 0.0f;
        Top2 ft;
        if (lid < nw) ft = s_top[lid];
        else { ft.m1 = -INFINITY; ft.m2 = -INFINITY; ft.i1 = -1; ft.i2 = -1; }

        #pragma unroll
        for (int off = nw / 2; off > 0; off >>= 1) {
            fsum += __shfl_xor_sync(FULL, fsum, off);
            Top2 o;
            o.m1 = __shfl_xor_sync(FULL, ft.m1, off);
            o.m2 = __shfl_xor_sync(FULL, ft.m2, off);
            o.i1 = __shfl_xor_sync(FULL, ft.i1, off);
            o.i2 = __shfl_xor_sync(FULL, ft.i2, off);
            top2_merge(ft, o);
        }

        if (lid == 0) {
            long long yv = y[row];
            // if argmax equals label, use runner-up
            float first = ((long long)ft.i1 == yv) ? ft.m2 : ft.m1;
            // faithful to reference: subtract the *logit* value from sum(exp)
            float second = logf(fsum - first);
            out[row] = first - second;
        }
    }
}

extern "C" void kernel_launch(void* const* d_in, const int* in_sizes, int n_in,
                              void* d_out, int out_size) {
    const float*      logits = (const float*)d_in[0];
    const long long*  y      = (const long long*)d_in[1];
    float*            out    = (float*)d_out;
    (void)in_sizes; (void)n_in; (void)out_size;

    fused_margin_kernel<<<2048, THREADS>>>(logits, y, out);
}

// round 3
// speedup vs baseline: 1.1843x; 1.1843x over previous
#include <cuda_runtime.h>
#include <math.h>

#define C_DIM    128000
#define C_VEC    (C_DIM / 4)         // 32000 float4 per row
#define B_ROWS   2048
#define SPLIT    5
#define CHUNK_V  (C_VEC / SPLIT)     // 6400 float4 per chunk
#define THREADS  256                 // 6400 / 256 = 25 iterations exactly

// partial per (row, split): x=sum_exp, y=m1, z=m2, w=unused
__device__ float4 g_partial[B_ROWS * SPLIT];

__device__ __forceinline__ void top2_val(float& m1, float& m2, float v) {
    float t  = fminf(m1, v);
    m1 = fmaxf(m1, v);
    m2 = fmaxf(m2, t);
}

__global__ __launch_bounds__(THREADS, 8)
void phase1_kernel(const float* __restrict__ logits) {
    const int unit  = blockIdx.x;            // 0 .. B_ROWS*SPLIT-1
    const int row   = unit / SPLIT;
    const int split = unit - row * SPLIT;

    const float4* __restrict__ p =
        reinterpret_cast<const float4*>(logits + (size_t)row * C_DIM)
        + split * CHUNK_V;

    const int tid = threadIdx.x;

    float sum = 0.0f;
    float m1 = -INFINITY, m2 = -INFINITY;

    #pragma unroll 5
    for (int j = tid; j < CHUNK_V; j += THREADS) {
        float4 v = p[j];
        sum += __expf(v.x);
        sum += __expf(v.y);
        sum += __expf(v.z);
        sum += __expf(v.w);
        top2_val(m1, m2, v.x);
        top2_val(m1, m2, v.y);
        top2_val(m1, m2, v.z);
        top2_val(m1, m2, v.w);
    }

    // ---- warp reduction ----
    const unsigned FULL = 0xFFFFFFFFu;
    #pragma unroll
    for (int off = 16; off > 0; off >>= 1) {
        sum += __shfl_xor_sync(FULL, sum, off);
        float om1 = __shfl_xor_sync(FULL, m1, off);
        float om2 = __shfl_xor_sync(FULL, m2, off);
        float nm1 = fmaxf(m1, om1);
        m2 = fmaxf(fminf(m1, om1), fmaxf(m2, om2));
        m1 = nm1;
    }

    // ---- cross-warp reduction ----
    __shared__ float s_sum[THREADS / 32];
    __shared__ float s_m1[THREADS / 32];
    __shared__ float s_m2[THREADS / 32];

    const int wid = tid >> 5;
    const int lid = tid & 31;
    if (lid == 0) { s_sum[wid] = sum; s_m1[wid] = m1; s_m2[wid] = m2; }
    __syncthreads();

    if (wid == 0) {
        const int nw = THREADS / 32;
        float fsum = (lid < nw) ? s_sum[lid] : 0.0f;
        float fm1  = (lid < nw) ? s_m1[lid]  : -INFINITY;
        float fm2  = (lid < nw) ? s_m2[lid]  : -INFINITY;

        #pragma unroll
        for (int off = nw / 2; off > 0; off >>= 1) {
            fsum += __shfl_xor_sync(FULL, fsum, off);
            float om1 = __shfl_xor_sync(FULL, fm1, off);
            float om2 = __shfl_xor_sync(FULL, fm2, off);
            float nm1 = fmaxf(fm1, om1);
            fm2 = fmaxf(fminf(fm1, om1), fmaxf(fm2, om2));
            fm1 = nm1;
        }

        if (lid == 0) {
            g_partial[unit] = make_float4(fsum, fm1, fm2, 0.0f);
        }
    }
}

__global__ void phase2_kernel(const float* __restrict__ logits,
                              const int* __restrict__ y,
                              float* __restrict__ out) {
    const int row = blockIdx.x * blockDim.x + threadIdx.x;
    if (row >= B_ROWS) return;

    float sum = 0.0f;
    float m1 = -INFINITY, m2 = -INFINITY;

    #pragma unroll
    for (int s = 0; s < SPLIT; s++) {
        float4 v = g_partial[row * SPLIT + s];
        sum += v.x;
        float nm1 = fmaxf(m1, v.y);
        m2 = fmaxf(fminf(m1, v.y), fmaxf(m2, v.z));
        m1 = nm1;
    }

    // y is int32 on-device (JAX default int); clamp defensively so any dtype
    // surprise can't produce an OOB gather.
    int yv = y[row];
    if (yv < 0)      yv = 0;
    if (yv >= C_DIM) yv = C_DIM - 1;
    const float vy = logits[(size_t)row * C_DIM + (size_t)yv];

    // y is argmax  <=>  logits[row][y] == global max (distinct random values)
    const float first = (vy == m1) ? m2 : m1;
    out[row] = first - logf(sum - first);
}

extern "C" void kernel_launch(void* const* d_in, const int* in_sizes, int n_in,
                              void* d_out, int out_size) {
    const float* logits = (const float*)d_in[0];
    const int*   y      = (const int*)d_in[1];
    float*       out    = (float*)d_out;
    (void)in_sizes; (void)n_in; (void)out_size;

    phase1_kernel<<<B_ROWS * SPLIT, THREADS>>>(logits);
    phase2_kernel<<<(B_ROWS + 255) / 256, 256>>>(logits, y, out);
}

// round 4
// speedup vs baseline: 1.1846x; 1.0002x over previous
#include <cuda_runtime.h>
#include <math.h>

#define C_DIM    128000
#define C_VEC    (C_DIM / 4)         // 32000 float4 per row
#define B_ROWS   2048
#define SPLIT    5
#define CHUNK_V  (C_VEC / SPLIT)     // 6400 float4 per chunk
#define THREADS  256                 // 6400 / 256 = 25 iterations exactly

// partial per (row, split): x=sum_exp, y=m1, z=m2, w=unused
__device__ float4 g_partial[B_ROWS * SPLIT];
// per-row arrival counter (zero-init at load; reset to 0 by the finishing
// block each call -> deterministic across graph replays)
__device__ unsigned int g_count[B_ROWS];

__device__ __forceinline__ void top2_val(float& m1, float& m2, float v) {
    float t  = fminf(m1, v);
    m1 = fmaxf(m1, v);
    m2 = fmaxf(m2, t);
}

__global__ __launch_bounds__(THREADS, 8)
void fused_kernel(const float* __restrict__ logits,
                  const int* __restrict__ y,
                  float* __restrict__ out) {
    const int unit  = blockIdx.x;            // 0 .. B_ROWS*SPLIT-1
    const int row   = unit / SPLIT;
    const int split = unit - row * SPLIT;

    const float4* __restrict__ p =
        reinterpret_cast<const float4*>(logits + (size_t)row * C_DIM)
        + split * CHUNK_V;

    const int tid = threadIdx.x;

    float sum = 0.0f;
    float m1 = -INFINITY, m2 = -INFINITY;

    #pragma unroll 5
    for (int j = tid; j < CHUNK_V; j += THREADS) {
        float4 v = p[j];
        sum += __expf(v.x);
        sum += __expf(v.y);
        sum += __expf(v.z);
        sum += __expf(v.w);
        top2_val(m1, m2, v.x);
        top2_val(m1, m2, v.y);
        top2_val(m1, m2, v.z);
        top2_val(m1, m2, v.w);
    }

    // ---- warp reduction ----
    const unsigned FULL = 0xFFFFFFFFu;
    #pragma unroll
    for (int off = 16; off > 0; off >>= 1) {
        sum += __shfl_xor_sync(FULL, sum, off);
        float om1 = __shfl_xor_sync(FULL, m1, off);
        float om2 = __shfl_xor_sync(FULL, m2, off);
        float nm1 = fmaxf(m1, om1);
        m2 = fmaxf(fminf(m1, om1), fmaxf(m2, om2));
        m1 = nm1;
    }

    // ---- cross-warp reduction ----
    __shared__ float s_sum[THREADS / 32];
    __shared__ float s_m1[THREADS / 32];
    __shared__ float s_m2[THREADS / 32];
    __shared__ unsigned int s_last;

    const int wid = tid >> 5;
    const int lid = tid & 31;
    if (lid == 0) { s_sum[wid] = sum; s_m1[wid] = m1; s_m2[wid] = m2; }
    __syncthreads();

    if (wid == 0) {
        const int nw = THREADS / 32;
        float fsum = (lid < nw) ? s_sum[lid] : 0.0f;
        float fm1  = (lid < nw) ? s_m1[lid]  : -INFINITY;
        float fm2  = (lid < nw) ? s_m2[lid]  : -INFINITY;

        #pragma unroll
        for (int off = nw / 2; off > 0; off >>= 1) {
            fsum += __shfl_xor_sync(FULL, fsum, off);
            float om1 = __shfl_xor_sync(FULL, fm1, off);
            float om2 = __shfl_xor_sync(FULL, fm2, off);
            float nm1 = fmaxf(fm1, om1);
            fm2 = fmaxf(fminf(fm1, om1), fmaxf(fm2, om2));
            fm1 = nm1;
        }

        if (lid == 0) {
            // publish this chunk's partial
            g_partial[unit] = make_float4(fsum, fm1, fm2, 0.0f);
            __threadfence();
            // signal arrival; last arriver finalizes the row
            unsigned int prev = atomicAdd(&g_count[row], 1u);
            s_last = (prev == SPLIT - 1) ? 1u : 0u;
        }
    }
    __syncthreads();

    if (s_last && tid == 0) {
        float tsum = 0.0f;
        float tm1 = -INFINITY, tm2 = -INFINITY;
        #pragma unroll
        for (int s = 0; s < SPLIT; s++) {
            float4 v = g_partial[row * SPLIT + s];
            tsum += v.x;
            float nm1 = fmaxf(tm1, v.y);
            tm2 = fmaxf(fminf(tm1, v.y), fmaxf(tm2, v.z));
            tm1 = nm1;
        }

        int yv = y[row];
        if (yv < 0)      yv = 0;
        if (yv >= C_DIM) yv = C_DIM - 1;
        const float vy = logits[(size_t)row * C_DIM + (size_t)yv];

        // y is argmax  <=>  logits[row][y] == global max (distinct values)
        const float first = (vy == tm1) ? tm2 : tm1;
        out[row] = first - logf(tsum - first);

        // reset counter for the next (graph-replayed) call
        g_count[row] = 0u;
    }
}

extern "C" void kernel_launch(void* const* d_in, const int* in_sizes, int n_in,
                              void* d_out, int out_size) {
    const float* logits = (const float*)d_in[0];
    const int*   y      = (const int*)d_in[1];
    float*       out    = (float*)d_out;
    (void)in_sizes; (void)n_in; (void)out_size;

    fused_kernel<<<B_ROWS * SPLIT, THREADS>>>(logits, y, out);
}